// round 2
// baseline (speedup 1.0000x reference)
#include <cuda_runtime.h>

// KMeansLayer: out[n,k] = softmax_k( (2*x.c_k - ||c_k||^2) / T ), T=0.1
// (||x||^2 cancels inside softmax.)
// x: [32*1024, 256] f32, centroids: [512, 256] f32, out: [32768, 512] f32.

#define N_ROWS   32768
#define KCL      512
#define DIM      256
#define M_TILE   32
#define DC       16          // D-chunk held in smem
#define CSTRIDE  516         // padded row stride for centroid smem chunk
#define LOG2E_F  1.4426950408889634f

__device__ float g_csq10[KCL];   // 10 * ||c_k||^2

// ---------------------------------------------------------------------------
// Packed f32x2 helpers (FFMA2 path — 2x fp32 FMA throughput on sm_103a)
// ---------------------------------------------------------------------------
__device__ __forceinline__ unsigned long long pack2(float lo, float hi) {
    unsigned long long r;
    asm("mov.b64 %0, {%1, %2};" : "=l"(r) : "f"(lo), "f"(hi));
    return r;
}
__device__ __forceinline__ void unpack2(unsigned long long v, float& lo, float& hi) {
    asm("mov.b64 {%0, %1}, %2;" : "=f"(lo), "=f"(hi) : "l"(v));
}
__device__ __forceinline__ void ffma2(unsigned long long& d,
                                      unsigned long long a,
                                      unsigned long long b) {
    asm("fma.rn.f32x2 %0, %1, %2, %0;" : "+l"(d) : "l"(a), "l"(b));
}

// ---------------------------------------------------------------------------
// Precompute 10*||c_k||^2 : one warp per cluster
// ---------------------------------------------------------------------------
__global__ void csq_kernel(const float* __restrict__ cent) {
    const int col  = blockIdx.x;
    const int lane = threadIdx.x;
    const float4* c4 = reinterpret_cast<const float4*>(cent) + col * (DIM / 4);
    float s = 0.f;
#pragma unroll
    for (int i = 0; i < 2; ++i) {
        float4 v = c4[lane + 32 * i];
        s += v.x * v.x + v.y * v.y + v.z * v.z + v.w * v.w;
    }
#pragma unroll
    for (int o = 16; o > 0; o >>= 1) s += __shfl_xor_sync(0xffffffffu, s, o);
    if (lane == 0) g_csq10[col] = 10.0f * s;
}

// ---------------------------------------------------------------------------
// Main fused GEMM + softmax kernel.
// CTA: 32 rows x 512 cols. 256 threads.
// thread(m_sub = tid>>5, n_sub = tid&31) owns rows m_sub*4..+3 and
// cols n_sub*4 + j*128 + k  (j<4, k<4)  => 4x16 register tile,
// stored as 32 packed f32x2 accumulators.
// Warp == one m_sub => the 32 lanes of a warp cover an entire output row,
// so the softmax reduction is pure warp shuffle.
// ---------------------------------------------------------------------------
__global__ __launch_bounds__(256, 2)
void kmeans_kernel(const float* __restrict__ x,
                   const float* __restrict__ cent,
                   float* __restrict__ out) {
    __shared__ float cs[DC * CSTRIDE];   // cs[d][col], padded stride
    __shared__ float xs[M_TILE * DC];    // xs[r][d]
    __shared__ float c10[KCL];

    const int tid  = threadIdx.x;
    const int msub = tid >> 5;
    const int nsub = tid & 31;
    const int row0 = blockIdx.x * M_TILE;

    for (int i = tid; i < KCL; i += 256) c10[i] = g_csq10[i];

    unsigned long long acc[4][8];
#pragma unroll
    for (int i = 0; i < 4; ++i)
#pragma unroll
        for (int p = 0; p < 8; ++p) acc[i][p] = 0ull;

    const float4* x4 = reinterpret_cast<const float4*>(x);
    const float4* c4 = reinterpret_cast<const float4*>(cent);

    for (int d0 = 0; d0 < DIM; d0 += DC) {
        // ---- load x chunk: 32 rows x 16 d = 128 float4 ----
        if (tid < 128) {
            const int r = tid >> 2, d4 = tid & 3;
            float4 v = x4[(row0 + r) * (DIM / 4) + (d0 >> 2) + d4];
            *reinterpret_cast<float4*>(&xs[r * DC + d4 * 4]) = v;
        }
        // ---- load centroid chunk: 512 cols x 16 d = 2048 float4 ----
#pragma unroll
        for (int i = 0; i < 8; ++i) {
            const int idx = tid + i * 256;     // 0..2047
            const int col = idx >> 2;
            const int d4  = idx & 3;
            float4 v = c4[col * (DIM / 4) + (d0 >> 2) + d4];
            const int d = d4 * 4;
            cs[(d + 0) * CSTRIDE + col] = v.x;
            cs[(d + 1) * CSTRIDE + col] = v.y;
            cs[(d + 2) * CSTRIDE + col] = v.z;
            cs[(d + 3) * CSTRIDE + col] = v.w;
        }
        __syncthreads();

        // ---- compute: 16 d-steps x (4 rows x 16 cols) via FFMA2 ----
#pragma unroll
        for (int dd = 0; dd < DC; ++dd) {
            unsigned long long cv[4][2];
#pragma unroll
            for (int j = 0; j < 4; ++j) {
                const ulonglong2 t = *reinterpret_cast<const ulonglong2*>(
                    &cs[dd * CSTRIDE + j * 128 + nsub * 4]);
                cv[j][0] = t.x;
                cv[j][1] = t.y;
            }
            unsigned long long xv[4];
#pragma unroll
            for (int i = 0; i < 4; ++i) {
                const float xf = xs[(msub * 4 + i) * DC + dd];
                xv[i] = pack2(xf, xf);
            }
#pragma unroll
            for (int i = 0; i < 4; ++i)
#pragma unroll
                for (int j = 0; j < 4; ++j) {
                    ffma2(acc[i][2 * j + 0], xv[i], cv[j][0]);
                    ffma2(acc[i][2 * j + 1], xv[i], cv[j][1]);
                }
        }
        __syncthreads();
    }

    // ---- fused softmax epilogue ----
#pragma unroll
    for (int i = 0; i < 4; ++i) {
        float l[16];
#pragma unroll
        for (int j = 0; j < 4; ++j) {
            float a, b, c, d;
            unpack2(acc[i][2 * j + 0], a, b);
            unpack2(acc[i][2 * j + 1], c, d);
            const int colb = j * 128 + nsub * 4;
            l[j * 4 + 0] = 20.f * a - c10[colb + 0];
            l[j * 4 + 1] = 20.f * b - c10[colb + 1];
            l[j * 4 + 2] = 20.f * c - c10[colb + 2];
            l[j * 4 + 3] = 20.f * d - c10[colb + 3];
        }
        float m = l[0];
#pragma unroll
        for (int k = 1; k < 16; ++k) m = fmaxf(m, l[k]);
#pragma unroll
        for (int o = 16; o > 0; o >>= 1)
            m = fmaxf(m, __shfl_xor_sync(0xffffffffu, m, o));

        float e[16];
        float s = 0.f;
#pragma unroll
        for (int k = 0; k < 16; ++k) {
            e[k] = exp2f((l[k] - m) * LOG2E_F);
            s += e[k];
        }
#pragma unroll
        for (int o = 16; o > 0; o >>= 1)
            s += __shfl_xor_sync(0xffffffffu, s, o);

        const float inv = 1.0f / s;
        const int row = row0 + msub * 4 + i;
#pragma unroll
        for (int j = 0; j < 4; ++j) {
            float4 v = make_float4(e[j * 4 + 0] * inv, e[j * 4 + 1] * inv,
                                   e[j * 4 + 2] * inv, e[j * 4 + 3] * inv);
            *reinterpret_cast<float4*>(&out[row * KCL + j * 128 + nsub * 4]) = v;
        }
    }
}

// ---------------------------------------------------------------------------
extern "C" void kernel_launch(void* const* d_in, const int* in_sizes, int n_in,
                              void* d_out, int out_size) {
    const float* x    = (const float*)d_in[0];
    const float* cent = (const float*)d_in[1];
    // Defensive: metadata order should be (x, centroids); swap if sizes say otherwise.
    if (n_in >= 2 && in_sizes[0] == KCL * DIM && in_sizes[1] == N_ROWS * DIM) {
        const float* t = x; x = cent; cent = t;
    }
    float* out = (float*)d_out;

    csq_kernel<<<KCL, 32>>>(cent);
    kmeans_kernel<<<N_ROWS / M_TILE, 256>>>(x, cent, out);
}

// round 4
// speedup vs baseline: 1.2234x; 1.2234x over previous
#include <cuda_runtime.h>
#include <cstdint>
#include <cstddef>

// KMeansLayer via legacy mma.sync (tf32, 2-way split, 3 passes) + fused softmax.
// out[n,k] = softmax_k( 20*(x_n . c_k) - 10*||c_k||^2 )   (||x||^2 cancels)
// x: [32768, 256] f32, centroids: [512, 256] f32, out: [32768, 512] f32.

#define NRTOT   32768
#define KCLUST  512
#define DDIM    256
#define MT      64          // rows per CTA
#define NK      32          // k8 steps (DDIM/8)
#define NST     3           // pipeline stages
#define LOG2E   1.4426950408889634f

#define A_STG_BYTES 4096    // 2 hl * 4 mtiles * 32 lanes * 4 regs * 4B
#define B_STG_BYTES 32768   // 2 hl * 64 ntiles * 32 lanes * 2 regs * 4B
#define STG_BYTES   (A_STG_BYTES + B_STG_BYTES)          // 36864
#define OFF_C10     (NST * STG_BYTES)                    // 110592
#define OFF_REDM    (OFF_C10 + 2048)
#define OFF_REDS    (OFF_REDM + 1024)                    // 64 rows * 4 nw * 4B
#define SMEM_TOTAL  (OFF_REDS + 1024)                    // 114688

// device scratch: pre-packed mma fragments
__device__ float g_csq10[KCLUST];
__device__ float g_Afrag[(size_t)512 * 32 * 2 * 4 * 32 * 4];  // 64 MB
__device__ float g_Bfrag[32 * 2 * 64 * 32 * 2];               // 1 MB

// ---------------------------------------------------------------- helpers
__device__ __forceinline__ uint32_t smem_u32(const void* p) {
    uint32_t a;
    asm("{ .reg .u64 t; cvta.to.shared.u64 t, %1; cvt.u32.u64 %0, t; }"
        : "=r"(a) : "l"(p));
    return a;
}
__device__ __forceinline__ float tf32_rna(float x) {
    float r;
    asm("cvt.rna.tf32.f32 %0, %1;" : "=f"(r) : "f"(x));
    return r;
}
__device__ __forceinline__ void cp16(uint32_t dst, const void* src) {
    asm volatile("cp.async.cg.shared.global [%0], [%1], 16;"
                 :: "r"(dst), "l"(__cvta_generic_to_global(src)) : "memory");
}
#define CP_COMMIT() asm volatile("cp.async.commit_group;" ::: "memory")
#define CP_WAIT(n)  asm volatile("cp.async.wait_group %0;" :: "n"(n) : "memory")

__device__ __forceinline__ void mma8(float* d, const uint4& a, const uint2& b) {
    asm("mma.sync.aligned.m16n8k8.row.col.f32.tf32.tf32.f32 "
        "{%0,%1,%2,%3}, {%4,%5,%6,%7}, {%8,%9}, {%0,%1,%2,%3};"
        : "+f"(d[0]), "+f"(d[1]), "+f"(d[2]), "+f"(d[3])
        : "r"(a.x), "r"(a.y), "r"(a.z), "r"(a.w), "r"(b.x), "r"(b.y));
}

// ------------------------------------------------------ prologue kernels
__global__ void csq_kernel(const float* __restrict__ cent) {
    const int col = blockIdx.x, lane = threadIdx.x;
    const float4* c4 = reinterpret_cast<const float4*>(cent) + col * (DDIM / 4);
    float s = 0.f;
#pragma unroll
    for (int i = 0; i < 2; ++i) {
        float4 v = c4[lane + 32 * i];
        s += v.x * v.x + v.y * v.y + v.z * v.z + v.w * v.w;
    }
#pragma unroll
    for (int o = 16; o > 0; o >>= 1) s += __shfl_xor_sync(0xffffffffu, s, o);
    if (lane == 0) g_csq10[col] = 10.0f * s;
}

// x -> fragment-packed tf32 hi/lo. Layout: [rb 512][kb 32][hl 2][mt 4][lane 32][reg 4]
__global__ void aconv_kernel(const float* __restrict__ x) {
    const int rb = blockIdx.x, kb = blockIdx.y;
    const int t = threadIdx.x;                  // 256
    const int hl = t >> 7, mt = (t >> 5) & 3, lane = t & 31;
    const int grp = lane >> 2, tig = lane & 3;
    float v4[4];
#pragma unroll
    for (int r = 0; r < 4; ++r) {
        const int row = rb * 64 + mt * 16 + grp + (r & 1) * 8;
        const int k   = kb * 8 + tig + (r >> 1) * 4;
        const float v = x[row * DDIM + k];
        const float hi = tf32_rna(v);
        v4[r] = hl ? tf32_rna(v - hi) : hi;
    }
    float4* dst = reinterpret_cast<float4*>(g_Afrag) +
                  ((((size_t)(rb * 32 + kb) * 2 + hl) * 4 + mt) * 32 + lane);
    *dst = make_float4(v4[0], v4[1], v4[2], v4[3]);
}

// centroids -> fragment-packed tf32 hi/lo. Layout: [kb 32][hl 2][nt 64][lane 32][reg 2]
__global__ void bconv_kernel(const float* __restrict__ cent) {
    const int g = blockIdx.x * 256 + threadIdx.x;   // 65536 threads
    const int kb = g >> 11, rest = g & 2047;
    const int nt = rest >> 5, lane = rest & 31;
    const int grp = lane >> 2, tig = lane & 3;
    const int n = nt * 8 + grp;
    float hi2[2], lo2[2];
#pragma unroll
    for (int r = 0; r < 2; ++r) {
        const float v = cent[n * DDIM + kb * 8 + tig + r * 4];
        hi2[r] = tf32_rna(v);
        lo2[r] = tf32_rna(v - hi2[r]);
    }
    float2* bh = reinterpret_cast<float2*>(g_Bfrag) +
                 ((((size_t)kb * 2 + 0) * 64 + nt) * 32 + lane);
    float2* bl = reinterpret_cast<float2*>(g_Bfrag) +
                 ((((size_t)kb * 2 + 1) * 64 + nt) * 32 + lane);
    *bh = make_float2(hi2[0], hi2[1]);
    *bl = make_float2(lo2[0], lo2[1]);
}

// ------------------------------------------------------------ main kernel
__device__ __forceinline__ void issue_stage(uint32_t sb, int s, int k,
                                            int rowblk, int tid) {
    const uint32_t dst0 = sb + s * STG_BYTES;
    const char* gA = reinterpret_cast<const char*>(g_Afrag) +
                     (size_t)(rowblk * 32 + k) * A_STG_BYTES;
    cp16(dst0 + tid * 16, gA + tid * 16);
    const char* gB = reinterpret_cast<const char*>(g_Bfrag) +
                     (size_t)k * B_STG_BYTES;
#pragma unroll
    for (int j = 0; j < 8; ++j) {
        const int o = (tid + j * 256) * 16;
        cp16(dst0 + A_STG_BYTES + o, gB + o);
    }
}

__global__ __launch_bounds__(256, 1)
void kmeans_mma(float* __restrict__ out) {
    extern __shared__ char smem[];
    const uint32_t sb = smem_u32(smem);
    const int tid = threadIdx.x;
    const int w = tid >> 5, lane = tid & 31;
    const int mw = w >> 2, nw = w & 3;          // warp tile: rows mw*32+, cols nw*128+
    const int grp = lane >> 2, tig = lane & 3;
    const int rowblk = blockIdx.x;

    float* c10s = reinterpret_cast<float*>(smem + OFF_C10);
    for (int i = tid; i < KCLUST; i += 256) c10s[i] = g_csq10[i];

    float acc[2][16][4];
#pragma unroll
    for (int mt = 0; mt < 2; ++mt)
#pragma unroll
        for (int nt = 0; nt < 16; ++nt)
#pragma unroll
            for (int r = 0; r < 4; ++r) acc[mt][nt][r] = 0.f;

    // pipeline prologue
#pragma unroll
    for (int s = 0; s < NST; ++s) {
        issue_stage(sb, s, s, rowblk, tid);
        CP_COMMIT();
    }

    for (int k = 0; k < NK; ++k) {
        const int s = k % NST;
        if (k <= NK - 3)      CP_WAIT(2);
        else if (k == NK - 2) CP_WAIT(1);
        else                  CP_WAIT(0);
        __syncthreads();

        const char* sA = smem + s * STG_BYTES;
        const char* sB = sA + A_STG_BYTES;

        uint4 ah[2], al[2];
#pragma unroll
        for (int mt = 0; mt < 2; ++mt) {
            ah[mt] = *reinterpret_cast<const uint4*>(
                sA + (((0 * 4 + (mw * 2 + mt)) * 32 + lane) << 4));
            al[mt] = *reinterpret_cast<const uint4*>(
                sA + (((1 * 4 + (mw * 2 + mt)) * 32 + lane) << 4));
        }
#pragma unroll
        for (int nt = 0; nt < 16; ++nt) {
            const uint2 bh = *reinterpret_cast<const uint2*>(
                sB + (((0 * 64 + nw * 16 + nt) * 32 + lane) << 3));
            const uint2 bl = *reinterpret_cast<const uint2*>(
                sB + (((1 * 64 + nw * 16 + nt) * 32 + lane) << 3));
#pragma unroll
            for (int mt = 0; mt < 2; ++mt) {
                mma8(acc[mt][nt], ah[mt], bh);   // hi*hi
                mma8(acc[mt][nt], ah[mt], bl);   // hi*lo
                mma8(acc[mt][nt], al[mt], bh);   // lo*hi
            }
        }
        __syncthreads();

        if (k + NST < NK) {
            issue_stage(sb, s, k + NST, rowblk, tid);
            CP_COMMIT();
        }
    }

    // ---------------- fused softmax epilogue ----------------
    // logits in-place
#pragma unroll
    for (int mt = 0; mt < 2; ++mt)
#pragma unroll
        for (int nt = 0; nt < 16; ++nt)
#pragma unroll
            for (int r = 0; r < 4; ++r) {
                const int col = nw * 128 + nt * 8 + 2 * tig + (r & 1);
                acc[mt][nt][r] = 20.f * acc[mt][nt][r] - c10s[col];
            }

    float* redM = reinterpret_cast<float*>(smem + OFF_REDM);
    float* redS = reinterpret_cast<float*>(smem + OFF_REDS);

    float mloc[4], sloc[4];
#pragma unroll
    for (int rid = 0; rid < 4; ++rid) {
        const int mt = rid >> 1, rh = rid & 1;
        float m = -1e30f;
#pragma unroll
        for (int nt = 0; nt < 16; ++nt) {
            m = fmaxf(m, acc[mt][nt][rh * 2 + 0]);
            m = fmaxf(m, acc[mt][nt][rh * 2 + 1]);
        }
        m = fmaxf(m, __shfl_xor_sync(0xffffffffu, m, 1));
        m = fmaxf(m, __shfl_xor_sync(0xffffffffu, m, 2));
        float s = 0.f;
#pragma unroll
        for (int nt = 0; nt < 16; ++nt) {
#pragma unroll
            for (int c = 0; c < 2; ++c) {
                const float e = exp2f((acc[mt][nt][rh * 2 + c] - m) * LOG2E);
                acc[mt][nt][rh * 2 + c] = e;     // reuse regs as exp values
                s += e;
            }
        }
        s += __shfl_xor_sync(0xffffffffu, s, 1);
        s += __shfl_xor_sync(0xffffffffu, s, 2);
        mloc[rid] = m;
        sloc[rid] = s;
        if (tig == 0) {
            const int row = mw * 32 + mt * 16 + rh * 8 + grp;
            redM[row * 4 + nw] = m;
            redS[row * 4 + nw] = s;
        }
    }
    __syncthreads();

#pragma unroll
    for (int rid = 0; rid < 4; ++rid) {
        const int mt = rid >> 1, rh = rid & 1;
        const int row = mw * 32 + mt * 16 + rh * 8 + grp;
        const float m0 = redM[row * 4 + 0], m1 = redM[row * 4 + 1];
        const float m2 = redM[row * 4 + 2], m3 = redM[row * 4 + 3];
        const float M = fmaxf(fmaxf(m0, m1), fmaxf(m2, m3));
        const float S = redS[row * 4 + 0] * exp2f((m0 - M) * LOG2E) +
                        redS[row * 4 + 1] * exp2f((m1 - M) * LOG2E) +
                        redS[row * 4 + 2] * exp2f((m2 - M) * LOG2E) +
                        redS[row * 4 + 3] * exp2f((m3 - M) * LOG2E);
        const float scale = exp2f((mloc[rid] - M) * LOG2E) / S;

        float* orow = out + (size_t)(rowblk * MT + row) * KCLUST + nw * 128;
#pragma unroll
        for (int nt = 0; nt < 16; ++nt) {
            float2 v;
            v.x = acc[mt][nt][rh * 2 + 0] * scale;
            v.y = acc[mt][nt][rh * 2 + 1] * scale;
            *reinterpret_cast<float2*>(orow + nt * 8 + 2 * tig) = v;
        }
    }
}

// ---------------------------------------------------------------- launch
extern "C" void kernel_launch(void* const* d_in, const int* in_sizes, int n_in,
                              void* d_out, int out_size) {
    const float* x = (const float*)d_in[0];
    const float* cent = (const float*)d_in[1];
    if (n_in >= 2 && in_sizes[0] == KCLUST * DDIM && in_sizes[1] == NRTOT * DDIM) {
        const float* t = x; x = cent; cent = t;
    }
    float* out = (float*)d_out;

    static int smem_set = 0;
    if (!smem_set) {
        cudaFuncSetAttribute(kmeans_mma,
                             cudaFuncAttributeMaxDynamicSharedMemorySize,
                             SMEM_TOTAL);
        smem_set = 1;
    }

    csq_kernel<<<KCLUST, 32>>>(cent);
    bconv_kernel<<<256, 256>>>(cent);
    aconv_kernel<<<dim3(NRTOT / MT, NK), 256>>>(x);
    kmeans_mma<<<NRTOT / MT, 256, SMEM_TOTAL>>>(out);
}